// round 14
// baseline (speedup 1.0000x reference)
#include <cuda_runtime.h>
#include <cuda_fp16.h>
#include <cstdint>

// binary_conv via mma.sync m16n8k16 fp16 (norm rel err ~2e-4 < 1e-3).
// x: [32,112,112,128] f32  w: [3,3,128,256] f32 -> sign(w)  out: [32,112,112,256] f32
// GEMM: M=401408, N=256, K=1152.
// CTA 128x128, warp tile 64x64 (4 warps, 2m x 2n), BK=32, 5-stage cp.async ring,
// issue-before-wait + wait<3> + ONE sync/stage (R12 ordering), 2 CTAs/SM.
// LDS/stage cut 48KB -> 32KB: smem port no longer co-saturated with tensor pipe.

#define N_  32
#define H_  112
#define W_  112
#define C_  128
#define CO_ 256
#define BM  128
#define BN  128
#define NCHUNK 36            // 9 taps * 4 chunks of 32 channels

#define NPIX (N_ * H_ * W_ * C_)      // 51380224

__device__ __align__(16) __half g_xp[NPIX];          // x in fp16
__device__ __align__(16) __half g_wb[9 * 128 * 256]; // sign(w) fp16, [pos][c][co]

// smem per stage: A 128 rows x 80B stride = 10240, B 32 rows x 272B = 8704
#define A_STRIDE_B 80
#define B_STRIDE_B 272
#define OFF_A 0
#define OFF_B 10240
#define STAGE_BYTES 18944
#define NSTAGES 5
#define SMEM_BYTES (NSTAGES * STAGE_BYTES)   // 94720 -> 2 CTAs/SM fits

// ---------------- PTX helpers (legal on plain sm_103 target) ----------------
__device__ __forceinline__ uint32_t smem_u32(const void* p) {
    uint32_t a;
    asm("{ .reg .u64 t; cvta.to.shared.u64 t, %1; cvt.u32.u64 %0, t; }" : "=r"(a) : "l"(p));
    return a;
}
__device__ __forceinline__ void cp16(uint32_t dst, const void* src, uint32_t srcsz) {
    asm volatile("cp.async.cg.shared.global [%0], [%1], 16, %2;"
                 :: "r"(dst), "l"(src), "r"(srcsz));
}
__device__ __forceinline__ void cp_commit() {
    asm volatile("cp.async.commit_group;" ::: "memory");
}
template <int N>
__device__ __forceinline__ void cp_wait() {
    asm volatile("cp.async.wait_group %0;" :: "n"(N) : "memory");
}
__device__ __forceinline__ void ldsm4(uint32_t* r, uint32_t addr) {
    asm volatile("ldmatrix.sync.aligned.m8n8.x4.shared.b16 {%0,%1,%2,%3}, [%4];"
                 : "=r"(r[0]), "=r"(r[1]), "=r"(r[2]), "=r"(r[3]) : "r"(addr));
}
__device__ __forceinline__ void ldsm4t(uint32_t* r, uint32_t addr) {
    asm volatile("ldmatrix.sync.aligned.m8n8.x4.trans.shared.b16 {%0,%1,%2,%3}, [%4];"
                 : "=r"(r[0]), "=r"(r[1]), "=r"(r[2]), "=r"(r[3]) : "r"(addr));
}
__device__ __forceinline__ void mma16816(float* d, const uint32_t* a, uint32_t b0, uint32_t b1) {
    asm volatile(
        "mma.sync.aligned.m16n8k16.row.col.f32.f16.f16.f32 "
        "{%0,%1,%2,%3}, {%4,%5,%6,%7}, {%8,%9}, {%0,%1,%2,%3};"
        : "+f"(d[0]), "+f"(d[1]), "+f"(d[2]), "+f"(d[3])
        : "r"(a[0]), "r"(a[1]), "r"(a[2]), "r"(a[3]), "r"(b0), "r"(b1));
}

// ---------------- merged prepack kernel ----------------
#define XBLK (NPIX / 4 / 256)            // 50176 blocks for x
__global__ void pack_kernel(const float* __restrict__ x, const float* __restrict__ w) {
    if (blockIdx.x < XBLK) {
        int i4 = blockIdx.x * 256 + threadIdx.x;
        float4 v = ((const float4*)x)[i4];
        __half2 p0 = __floats2half2_rn(v.x, v.y);
        __half2 p1 = __floats2half2_rn(v.z, v.w);
        ((uint2*)g_xp)[i4] = make_uint2(*(uint32_t*)&p0, *(uint32_t*)&p1);
    } else {
        int idx = (blockIdx.x - XBLK) * 256 + threadIdx.x;
        if (idx < 9 * 128 * 256) {
            float v = w[idx];                     // [pos][c][co] contiguous
            float s = (v > 0.f) ? 1.f : ((v < 0.f) ? -1.f : 0.f);
            g_wb[idx] = __float2half(s);
        }
    }
}

// ---------------- main kernel ----------------
__global__ __launch_bounds__(128, 2)
void bconv_mma_kernel(float* __restrict__ out)
{
    extern __shared__ unsigned char smem[];
    const uint32_t sb = smem_u32(smem);
    const int tid = threadIdx.x;
    const int lane = tid & 31;
    const int wid = tid >> 5;        // 0..3
    const int wm = wid & 1;          // rows wm*64
    const int wn = wid >> 1;         // cols wn*64
    const int m0 = blockIdx.y * BM;
    const int n0 = blockIdx.x * BN;

    // A loader coords: 1 thread per row (128 rows), 32 channels = 64B each
    const int m  = m0 + tid;
    const int b  = m / (H_ * W_);
    const int rm = m - b * (H_ * W_);
    const int hh = rm / W_;
    const int ww = rm - hh * W_;
    // B loader coords: 4 threads per k-row, 32 cols (64B) each -> 32 rows x 128 cols
    const int bkr  = tid >> 2;        // 0..31 k-row
    const int bcg  = (tid & 3) * 32;  // col group (0,32,64,96)

    float acc[4][8][4];
#pragma unroll
    for (int a = 0; a < 4; ++a)
#pragma unroll
        for (int j = 0; j < 8; ++j)
#pragma unroll
            for (int q = 0; q < 4; ++q) acc[a][j][q] = 0.f;

    // ---- chunk loader (one commit_group per call) ----
    auto issue = [&](int s) {
        const int pos = s >> 2, cc = s & 3;
        const int kh = pos / 3, kw = pos - kh * 3;
        const uint32_t base = sb + (uint32_t)(s % NSTAGES) * STAGE_BYTES;
        // A: row tid, channels cc*32 .. +31 (64B = 4 cp16)
        {
            const int hin = hh + kh - 1, win = ww + kw - 1;
            const bool valid = (hin >= 0) && (hin < H_) && (win >= 0) && (win < W_);
            const uint32_t sz = valid ? 16u : 0u;
            const size_t p = (((size_t)(b * H_ + hin)) * W_ + win) * C_ + cc * 32;
            const uint32_t dA = base + OFF_A + (uint32_t)tid * A_STRIDE_B;
#pragma unroll
            for (int q = 0; q < 4; ++q)
                cp16(dA + q * 16, g_xp + p + q * 8, sz);
        }
        // B: 32 k-rows x 128 n (fp16), pre-binarized
        {
            const size_t rb = ((size_t)(pos * C_ + cc * 32 + bkr)) * CO_ + n0 + bcg;
            const uint32_t dB = base + OFF_B + (uint32_t)bkr * B_STRIDE_B + (uint32_t)bcg * 2;
#pragma unroll
            for (int q = 0; q < 4; ++q)
                cp16(dB + q * 16, g_wb + rb + q * 8, 16u);
        }
        cp_commit();
    };

    // ldmatrix lane addressing
    const int lr8 = (lane & 7) + ((lane >> 3) & 1) * 8;
    const int lh8 = lane >> 4;

    issue(0);
    issue(1);
    issue(2);

    for (int s = 0; s < NCHUNK; ++s) {
        // issue next stage BEFORE waiting (burst overlaps the wait).
        // Writes slot (s+3)%5; slowest concurrent readers use slot (s-1)%5 -> disjoint.
        if (s + 3 < NCHUNK) issue(s + 3);

        if      (s <= NCHUNK - 4) cp_wait<3>();
        else if (s == NCHUNK - 3) cp_wait<2>();
        else if (s == NCHUNK - 2) cp_wait<1>();
        else                      cp_wait<0>();
        __syncthreads();        // single sync per stage

        const uint32_t base = sb + (uint32_t)(s % NSTAGES) * STAGE_BYTES;
        const uint32_t Aa = base + OFF_A + (uint32_t)(wm * 64) * A_STRIDE_B;
        const uint32_t Bb = base + OFF_B + (uint32_t)(wn * 64) * 2;

#pragma unroll
        for (int ks = 0; ks < 2; ++ks) {
            uint32_t af[4][4], bf[4][4];
#pragma unroll
            for (int mt = 0; mt < 4; ++mt) {
                const uint32_t ao = (uint32_t)(mt * 16 + lr8) * A_STRIDE_B + ks * 32 + lh8 * 16;
                ldsm4(af[mt], Aa + ao);
            }
#pragma unroll
            for (int jn = 0; jn < 4; ++jn) {
                const uint32_t bo = (uint32_t)(ks * 16 + lr8) * B_STRIDE_B + jn * 32 + lh8 * 16;
                ldsm4t(bf[jn], Bb + bo);
            }
#pragma unroll
            for (int mt = 0; mt < 4; ++mt)
#pragma unroll
                for (int j = 0; j < 8; ++j) {
                    const uint32_t b0 = bf[j >> 1][(j & 1) * 2];
                    const uint32_t b1 = bf[j >> 1][(j & 1) * 2 + 1];
                    mma16816(acc[mt][j], af[mt], b0, b1);
                }
        }
    }

    // ---- epilogue: direct gmem stores ----
    const int qr = lane >> 2, qc = lane & 3;
#pragma unroll
    for (int mt = 0; mt < 4; ++mt) {
        const int mrow = m0 + wm * 64 + mt * 16 + qr;
        float* o0 = out + (size_t)mrow * CO_ + n0 + wn * 64;
        float* o1 = out + (size_t)(mrow + 8) * CO_ + n0 + wn * 64;
#pragma unroll
        for (int j = 0; j < 8; ++j) {
            *(float2*)(o0 + j * 8 + qc * 2) = make_float2(acc[mt][j][0], acc[mt][j][1]);
            *(float2*)(o1 + j * 8 + qc * 2) = make_float2(acc[mt][j][2], acc[mt][j][3]);
        }
    }
}

extern "C" void kernel_launch(void* const* d_in, const int* in_sizes, int n_in,
                              void* d_out, int out_size)
{
    (void)in_sizes; (void)n_in; (void)out_size;
    const float* x = (const float*)d_in[0];
    const float* w = (const float*)d_in[1];
    float* out = (float*)d_out;

    cudaFuncSetAttribute(bconv_mma_kernel,
                         cudaFuncAttributeMaxDynamicSharedMemorySize, SMEM_BYTES);

    const int wblk = (9 * 128 * 256 + 255) / 256;      // 1152
    pack_kernel<<<XBLK + wblk, 256>>>(x, w);

    const int M = N_ * H_ * W_;                 // 401408
    dim3 grid(CO_ / BN, M / BM);                // (2, 3136)
    bconv_mma_kernel<<<grid, 128, SMEM_BYTES>>>(out);
}

// round 15
// speedup vs baseline: 1.1669x; 1.1669x over previous
#include <cuda_runtime.h>
#include <cuda_fp16.h>
#include <cstdint>

// binary_conv via mma.sync m16n8k16 fp16 (norm rel err ~2e-4 < 1e-3).
// x: [32,112,112,128] f32  w: [3,3,128,256] f32 -> sign(w)  out: [32,112,112,256] f32
// GEMM: M=401408, N=256, K=1152.
// CTA 128x256 (full Cout), 512 threads, warp tile 32x64 (16 warps, 4m x 4n),
// BK=32, 5-stage cp.async ring, issue-before-wait + wait<3> + ONE sync/stage.
// vs R12: A loaded once per stage (not per n-block) -> L2/STS traffic -31%.

#define N_  32
#define H_  112
#define W_  112
#define C_  128
#define CO_ 256
#define BM  128
#define NCHUNK 36            // 9 taps * 4 chunks of 32 channels

#define NPIX (N_ * H_ * W_ * C_)      // 51380224

__device__ __align__(16) __half g_xp[NPIX];          // x in fp16
__device__ __align__(16) __half g_wb[9 * 128 * 256]; // sign(w) fp16, [pos][c][co]

// smem per stage: A 128 rows x 80B stride = 10240, B 32 rows x 528B = 16896
#define A_STRIDE_B 80
#define B_STRIDE_B 528
#define OFF_A 0
#define OFF_B 10240
#define STAGE_BYTES 27136
#define NSTAGES 5
#define SMEM_BYTES (NSTAGES * STAGE_BYTES)   // 135680 < 227KB

// ---------------- PTX helpers (legal on plain sm_103 target) ----------------
__device__ __forceinline__ uint32_t smem_u32(const void* p) {
    uint32_t a;
    asm("{ .reg .u64 t; cvta.to.shared.u64 t, %1; cvt.u32.u64 %0, t; }" : "=r"(a) : "l"(p));
    return a;
}
__device__ __forceinline__ void cp16(uint32_t dst, const void* src, uint32_t srcsz) {
    asm volatile("cp.async.cg.shared.global [%0], [%1], 16, %2;"
                 :: "r"(dst), "l"(src), "r"(srcsz));
}
__device__ __forceinline__ void cp_commit() {
    asm volatile("cp.async.commit_group;" ::: "memory");
}
template <int N>
__device__ __forceinline__ void cp_wait() {
    asm volatile("cp.async.wait_group %0;" :: "n"(N) : "memory");
}
__device__ __forceinline__ void ldsm4(uint32_t* r, uint32_t addr) {
    asm volatile("ldmatrix.sync.aligned.m8n8.x4.shared.b16 {%0,%1,%2,%3}, [%4];"
                 : "=r"(r[0]), "=r"(r[1]), "=r"(r[2]), "=r"(r[3]) : "r"(addr));
}
__device__ __forceinline__ void ldsm4t(uint32_t* r, uint32_t addr) {
    asm volatile("ldmatrix.sync.aligned.m8n8.x4.trans.shared.b16 {%0,%1,%2,%3}, [%4];"
                 : "=r"(r[0]), "=r"(r[1]), "=r"(r[2]), "=r"(r[3]) : "r"(addr));
}
__device__ __forceinline__ void mma16816(float* d, const uint32_t* a, uint32_t b0, uint32_t b1) {
    asm volatile(
        "mma.sync.aligned.m16n8k16.row.col.f32.f16.f16.f32 "
        "{%0,%1,%2,%3}, {%4,%5,%6,%7}, {%8,%9}, {%0,%1,%2,%3};"
        : "+f"(d[0]), "+f"(d[1]), "+f"(d[2]), "+f"(d[3])
        : "r"(a[0]), "r"(a[1]), "r"(a[2]), "r"(a[3]), "r"(b0), "r"(b1));
}

// ---------------- merged prepack kernel ----------------
#define XBLK (NPIX / 4 / 256)            // 50176 blocks for x
__global__ void pack_kernel(const float* __restrict__ x, const float* __restrict__ w) {
    if (blockIdx.x < XBLK) {
        int i4 = blockIdx.x * 256 + threadIdx.x;
        float4 v = ((const float4*)x)[i4];
        __half2 p0 = __floats2half2_rn(v.x, v.y);
        __half2 p1 = __floats2half2_rn(v.z, v.w);
        ((uint2*)g_xp)[i4] = make_uint2(*(uint32_t*)&p0, *(uint32_t*)&p1);
    } else {
        int idx = (blockIdx.x - XBLK) * 256 + threadIdx.x;
        if (idx < 9 * 128 * 256) {
            float v = w[idx];                     // [pos][c][co] contiguous
            float s = (v > 0.f) ? 1.f : ((v < 0.f) ? -1.f : 0.f);
            g_wb[idx] = __float2half(s);
        }
    }
}

// ---------------- main kernel ----------------
__global__ __launch_bounds__(512, 1)
void bconv_mma_kernel(float* __restrict__ out)
{
    extern __shared__ unsigned char smem[];
    const uint32_t sb = smem_u32(smem);
    const int tid = threadIdx.x;
    const int lane = tid & 31;
    const int wid = tid >> 5;        // 0..15
    const int wm = wid & 3;          // 4 m-groups: rows wm*32
    const int wn = wid >> 2;         // 4 n-groups: cols wn*64
    const int m0 = blockIdx.x * BM;

    // A loader coords: 4 threads per row (128 rows), 16B (8 ch) each
    const int lr_row = tid >> 2;
    const int lq     = tid & 3;
    const int m  = m0 + lr_row;
    const int b  = m / (H_ * W_);
    const int rm = m - b * (H_ * W_);
    const int hh = rm / W_;
    const int ww = rm - hh * W_;
    // B loader coords: 16 threads per k-row (32 rows), 32B (16 cols) each
    const int bkr  = tid >> 4;        // 0..31 k-row
    const int bcg  = (tid & 15) * 16; // col group (x16 cols)

    float acc[2][8][4];
#pragma unroll
    for (int a = 0; a < 2; ++a)
#pragma unroll
        for (int j = 0; j < 8; ++j)
#pragma unroll
            for (int q = 0; q < 4; ++q) acc[a][j][q] = 0.f;

    // ---- chunk loader (one commit_group per call) ----
    auto issue = [&](int s) {
        const int pos = s >> 2, cc = s & 3;
        const int kh = pos / 3, kw = pos - kh * 3;
        const uint32_t base = sb + (uint32_t)(s % NSTAGES) * STAGE_BYTES;
        // A: row lr_row, channels cc*32 + lq*8 .. +7 (one cp16)
        {
            const int hin = hh + kh - 1, win = ww + kw - 1;
            const bool valid = (hin >= 0) && (hin < H_) && (win >= 0) && (win < W_);
            const uint32_t sz = valid ? 16u : 0u;
            const size_t p = (((size_t)(b * H_ + hin)) * W_ + win) * C_ + cc * 32 + lq * 8;
            const uint32_t dA = base + OFF_A + (uint32_t)lr_row * A_STRIDE_B + (uint32_t)lq * 16;
            cp16(dA, g_xp + p, sz);
        }
        // B: 32 k-rows x 256 n (fp16), pre-binarized; full Cout
        {
            const size_t rb = ((size_t)(pos * C_ + cc * 32 + bkr)) * CO_ + bcg;
            const uint32_t dB = base + OFF_B + (uint32_t)bkr * B_STRIDE_B + (uint32_t)bcg * 2;
            cp16(dB,      g_wb + rb,     16u);
            cp16(dB + 16, g_wb + rb + 8, 16u);
        }
        cp_commit();
    };

    // ldmatrix lane addressing
    const int lr8 = (lane & 7) + ((lane >> 3) & 1) * 8;
    const int lh8 = lane >> 4;

    issue(0);
    issue(1);
    issue(2);

    for (int s = 0; s < NCHUNK; ++s) {
        // issue next stage BEFORE waiting (burst overlaps the wait).
        // Writes slot (s+3)%5; slowest concurrent readers use slot (s-1)%5 -> disjoint.
        if (s + 3 < NCHUNK) issue(s + 3);

        if      (s <= NCHUNK - 4) cp_wait<3>();
        else if (s == NCHUNK - 3) cp_wait<2>();
        else if (s == NCHUNK - 2) cp_wait<1>();
        else                      cp_wait<0>();
        __syncthreads();        // single sync per stage

        const uint32_t base = sb + (uint32_t)(s % NSTAGES) * STAGE_BYTES;
        const uint32_t Aa = base + OFF_A + (uint32_t)(wm * 32) * A_STRIDE_B;
        const uint32_t Bb = base + OFF_B + (uint32_t)(wn * 64) * 2;

#pragma unroll
        for (int ks = 0; ks < 2; ++ks) {
            uint32_t af[2][4], bf[4][4];
#pragma unroll
            for (int mt = 0; mt < 2; ++mt) {
                const uint32_t ao = (uint32_t)(mt * 16 + lr8) * A_STRIDE_B + ks * 32 + lh8 * 16;
                ldsm4(af[mt], Aa + ao);
            }
#pragma unroll
            for (int jn = 0; jn < 4; ++jn) {
                const uint32_t bo = (uint32_t)(ks * 16 + lr8) * B_STRIDE_B + jn * 32 + lh8 * 16;
                ldsm4t(bf[jn], Bb + bo);
            }
#pragma unroll
            for (int mt = 0; mt < 2; ++mt)
#pragma unroll
                for (int j = 0; j < 8; ++j) {
                    const uint32_t b0 = bf[j >> 1][(j & 1) * 2];
                    const uint32_t b1 = bf[j >> 1][(j & 1) * 2 + 1];
                    mma16816(acc[mt][j], af[mt], b0, b1);
                }
        }
    }

    // ---- epilogue: direct gmem stores ----
    const int qr = lane >> 2, qc = lane & 3;
#pragma unroll
    for (int mt = 0; mt < 2; ++mt) {
        const int mrow = m0 + wm * 32 + mt * 16 + qr;
        float* o0 = out + (size_t)mrow * CO_ + wn * 64;
        float* o1 = out + (size_t)(mrow + 8) * CO_ + wn * 64;
#pragma unroll
        for (int j = 0; j < 8; ++j) {
            *(float2*)(o0 + j * 8 + qc * 2) = make_float2(acc[mt][j][0], acc[mt][j][1]);
            *(float2*)(o1 + j * 8 + qc * 2) = make_float2(acc[mt][j][2], acc[mt][j][3]);
        }
    }
}

extern "C" void kernel_launch(void* const* d_in, const int* in_sizes, int n_in,
                              void* d_out, int out_size)
{
    (void)in_sizes; (void)n_in; (void)out_size;
    const float* x = (const float*)d_in[0];
    const float* w = (const float*)d_in[1];
    float* out = (float*)d_out;

    cudaFuncSetAttribute(bconv_mma_kernel,
                         cudaFuncAttributeMaxDynamicSharedMemorySize, SMEM_BYTES);

    const int wblk = (9 * 128 * 256 + 255) / 256;      // 1152
    pack_kernel<<<XBLK + wblk, 256>>>(x, w);

    const int M = N_ * H_ * W_;                 // 401408
    bconv_mma_kernel<<<M / BM, 512, SMEM_BYTES>>>(out);
}

// round 16
// speedup vs baseline: 1.3045x; 1.1178x over previous
#include <cuda_runtime.h>
#include <cuda_fp16.h>
#include <cstdint>

// binary_conv via mma.sync m16n8k16 fp16 (norm rel err ~2e-4 < 1e-3).
// x: [32,112,112,128] f32  w: [3,3,128,256] f32 -> sign(w)  out: [32,112,112,256] f32
// GEMM: M=401408, N=256, K=1152.
// CTA 128x128, warp tile 32x64 (8 warps, 4m x 2n), BK=32, SIX-stage cp.async ring,
// issue-before-wait + wait<4> + ONE sync/stage, ks-staggered warps, 2 CTAs/SM.

#define N_  32
#define H_  112
#define W_  112
#define C_  128
#define CO_ 256
#define BM  128
#define BN  128
#define NCHUNK 36            // 9 taps * 4 chunks of 32 channels

#define NPIX (N_ * H_ * W_ * C_)      // 51380224

__device__ __align__(16) __half g_xp[NPIX];          // x in fp16
__device__ __align__(16) __half g_wb[9 * 128 * 256]; // sign(w) fp16, [pos][c][co]

// smem per stage: A 128 rows x 80B stride = 10240, B 32 rows x 272B = 8704
#define A_STRIDE_B 80
#define B_STRIDE_B 272
#define OFF_A 0
#define OFF_B 10240
#define STAGE_BYTES 18944
#define NSTAGES 6
#define SMEM_BYTES (NSTAGES * STAGE_BYTES)   // 113664/CTA; 2 CTAs = 227328 <= 228KB

// ---------------- PTX helpers (legal on plain sm_103 target) ----------------
__device__ __forceinline__ uint32_t smem_u32(const void* p) {
    uint32_t a;
    asm("{ .reg .u64 t; cvta.to.shared.u64 t, %1; cvt.u32.u64 %0, t; }" : "=r"(a) : "l"(p));
    return a;
}
__device__ __forceinline__ void cp16(uint32_t dst, const void* src, uint32_t srcsz) {
    asm volatile("cp.async.cg.shared.global [%0], [%1], 16, %2;"
                 :: "r"(dst), "l"(src), "r"(srcsz));
}
__device__ __forceinline__ void cp_commit() {
    asm volatile("cp.async.commit_group;" ::: "memory");
}
template <int N>
__device__ __forceinline__ void cp_wait() {
    asm volatile("cp.async.wait_group %0;" :: "n"(N) : "memory");
}
__device__ __forceinline__ void ldsm4(uint32_t* r, uint32_t addr) {
    asm volatile("ldmatrix.sync.aligned.m8n8.x4.shared.b16 {%0,%1,%2,%3}, [%4];"
                 : "=r"(r[0]), "=r"(r[1]), "=r"(r[2]), "=r"(r[3]) : "r"(addr));
}
__device__ __forceinline__ void ldsm4t(uint32_t* r, uint32_t addr) {
    asm volatile("ldmatrix.sync.aligned.m8n8.x4.trans.shared.b16 {%0,%1,%2,%3}, [%4];"
                 : "=r"(r[0]), "=r"(r[1]), "=r"(r[2]), "=r"(r[3]) : "r"(addr));
}
__device__ __forceinline__ void mma16816(float* d, const uint32_t* a, uint32_t b0, uint32_t b1) {
    asm volatile(
        "mma.sync.aligned.m16n8k16.row.col.f32.f16.f16.f32 "
        "{%0,%1,%2,%3}, {%4,%5,%6,%7}, {%8,%9}, {%0,%1,%2,%3};"
        : "+f"(d[0]), "+f"(d[1]), "+f"(d[2]), "+f"(d[3])
        : "r"(a[0]), "r"(a[1]), "r"(a[2]), "r"(a[3]), "r"(b0), "r"(b1));
}

// ---------------- merged prepack kernel ----------------
#define XBLK (NPIX / 4 / 256)            // 50176 blocks for x
__global__ void pack_kernel(const float* __restrict__ x, const float* __restrict__ w) {
    if (blockIdx.x < XBLK) {
        int i4 = blockIdx.x * 256 + threadIdx.x;
        float4 v = ((const float4*)x)[i4];
        __half2 p0 = __floats2half2_rn(v.x, v.y);
        __half2 p1 = __floats2half2_rn(v.z, v.w);
        ((uint2*)g_xp)[i4] = make_uint2(*(uint32_t*)&p0, *(uint32_t*)&p1);
    } else {
        int idx = (blockIdx.x - XBLK) * 256 + threadIdx.x;
        if (idx < 9 * 128 * 256) {
            float v = w[idx];                     // [pos][c][co] contiguous
            float s = (v > 0.f) ? 1.f : ((v < 0.f) ? -1.f : 0.f);
            g_wb[idx] = __float2half(s);
        }
    }
}

// ---------------- main kernel ----------------
__global__ __launch_bounds__(256, 2)
void bconv_mma_kernel(float* __restrict__ out)
{
    extern __shared__ unsigned char smem[];
    const uint32_t sb = smem_u32(smem);
    const int tid = threadIdx.x;
    const int lane = tid & 31;
    const int wid = tid >> 5;
    const int wm = wid & 3;          // 0..3 : rows wm*32
    const int wn = wid >> 2;         // 0..1 : cols wn*64
    const int m0 = blockIdx.y * BM;
    const int n0 = blockIdx.x * BN;

    // A loader coords: 2 threads per row, 16 channels (32B) each half
    const int lr_row = tid >> 1;
    const int lhalf  = tid & 1;
    const int m  = m0 + lr_row;
    const int b  = m / (H_ * W_);
    const int rm = m - b * (H_ * W_);
    const int hh = rm / W_;
    const int ww = rm - hh * W_;
    // B loader coords: 8 threads per k-row, 16 cols (32B) each -> 32 rows x 128 cols
    const int bkr  = tid >> 3;        // 0..31 k-row
    const int bcg  = (tid & 7) * 16;  // col group

    float acc[2][8][4];
#pragma unroll
    for (int a = 0; a < 2; ++a)
#pragma unroll
        for (int j = 0; j < 8; ++j)
#pragma unroll
            for (int q = 0; q < 4; ++q) acc[a][j][q] = 0.f;

    // ---- chunk loader (one commit_group per call) ----
    auto issue = [&](int s) {
        const int pos = s >> 2, cc = s & 3;
        const int kh = pos / 3, kw = pos - kh * 3;
        const uint32_t base = sb + (uint32_t)(s % NSTAGES) * STAGE_BYTES;
        // A: row lr_row, channels cc*32 + lhalf*16 .. +15
        {
            const int hin = hh + kh - 1, win = ww + kw - 1;
            const bool valid = (hin >= 0) && (hin < H_) && (win >= 0) && (win < W_);
            const uint32_t sz = valid ? 16u : 0u;
            const size_t p = (((size_t)(b * H_ + hin)) * W_ + win) * C_ + cc * 32 + lhalf * 16;
            const uint32_t dA = base + OFF_A + (uint32_t)lr_row * A_STRIDE_B + (uint32_t)lhalf * 32;
            cp16(dA,      g_xp + p,     sz);
            cp16(dA + 16, g_xp + p + 8, sz);
        }
        // B: 32 k-rows x 128 n (fp16), pre-binarized
        {
            const size_t rb = ((size_t)(pos * C_ + cc * 32 + bkr)) * CO_ + n0 + bcg;
            const uint32_t dB = base + OFF_B + (uint32_t)bkr * B_STRIDE_B + (uint32_t)bcg * 2;
            cp16(dB,      g_wb + rb,     16u);
            cp16(dB + 16, g_wb + rb + 8, 16u);
        }
        cp_commit();
    };

    // ldmatrix lane addressing
    const int lr8 = (lane & 7) + ((lane >> 3) & 1) * 8;
    const int lh8 = lane >> 4;
    const int ksStart = wid & 1;     // stagger: odd warps do ks=1 first

    issue(0);
    issue(1);
    issue(2);
    issue(3);

    for (int s = 0; s < NCHUNK; ++s) {
        // issue next stage BEFORE waiting (burst overlaps the wait).
        // Writes slot (s+4)%6; slowest concurrent readers use slot (s-1)%6 -> disjoint.
        if (s + 4 < NCHUNK) issue(s + 4);

        if      (s <= NCHUNK - 5) cp_wait<4>();
        else if (s == NCHUNK - 4) cp_wait<3>();
        else if (s == NCHUNK - 3) cp_wait<2>();
        else if (s == NCHUNK - 2) cp_wait<1>();
        else                      cp_wait<0>();
        __syncthreads();        // single sync per stage

        const uint32_t base = sb + (uint32_t)(s % NSTAGES) * STAGE_BYTES;
        const uint32_t Aa = base + OFF_A + (uint32_t)(wm * 32) * A_STRIDE_B;
        const uint32_t Bb = base + OFF_B + (uint32_t)(wn * 64) * 2;

#pragma unroll
        for (int kk = 0; kk < 2; ++kk) {
            const int ks = ksStart ^ kk;   // accumulation order commutes across ks
            uint32_t af[2][4], bf[4][4];
#pragma unroll
            for (int mt = 0; mt < 2; ++mt) {
                const uint32_t ao = (uint32_t)(mt * 16 + lr8) * A_STRIDE_B + ks * 32 + lh8 * 16;
                ldsm4(af[mt], Aa + ao);
            }
#pragma unroll
            for (int jn = 0; jn < 4; ++jn) {
                const uint32_t bo = (uint32_t)(ks * 16 + lr8) * B_STRIDE_B + jn * 32 + lh8 * 16;
                ldsm4t(bf[jn], Bb + bo);
            }
#pragma unroll
            for (int mt = 0; mt < 2; ++mt)
#pragma unroll
                for (int j = 0; j < 8; ++j) {
                    const uint32_t b0 = bf[j >> 1][(j & 1) * 2];
                    const uint32_t b1 = bf[j >> 1][(j & 1) * 2 + 1];
                    mma16816(acc[mt][j], af[mt], b0, b1);
                }
        }
    }

    // ---- epilogue: direct gmem stores ----
    const int qr = lane >> 2, qc = lane & 3;
#pragma unroll
    for (int mt = 0; mt < 2; ++mt) {
        const int mrow = m0 + wm * 32 + mt * 16 + qr;
        float* o0 = out + (size_t)mrow * CO_ + n0 + wn * 64;
        float* o1 = out + (size_t)(mrow + 8) * CO_ + n0 + wn * 64;
#pragma unroll
        for (int j = 0; j < 8; ++j) {
            *(float2*)(o0 + j * 8 + qc * 2) = make_float2(acc[mt][j][0], acc[mt][j][1]);
            *(float2*)(o1 + j * 8 + qc * 2) = make_float2(acc[mt][j][2], acc[mt][j][3]);
        }
    }
}

extern "C" void kernel_launch(void* const* d_in, const int* in_sizes, int n_in,
                              void* d_out, int out_size)
{
    (void)in_sizes; (void)n_in; (void)out_size;
    const float* x = (const float*)d_in[0];
    const float* w = (const float*)d_in[1];
    float* out = (float*)d_out;

    cudaFuncSetAttribute(bconv_mma_kernel,
                         cudaFuncAttributeMaxDynamicSharedMemorySize, SMEM_BYTES);

    const int wblk = (9 * 128 * 256 + 255) / 256;      // 1152
    pack_kernel<<<XBLK + wblk, 256>>>(x, w);

    const int M = N_ * H_ * W_;                 // 401408
    dim3 grid(CO_ / BN, M / BM);                // (2, 3136)
    bconv_mma_kernel<<<grid, 256, SMEM_BYTES>>>(out);
}